// round 1
// baseline (speedup 1.0000x reference)
#include <cuda_runtime.h>
#include <cstdint>

// Problem constants: x[S,B,I] fp32, W[I,4H], U[H,4H], bias[4H]
#define S_LEN 2048
#define NB 64
#define NI 512
#define NH 512
#define KTOT 1024          // fused K = I + H
#define NCTA 128           // <= SM count -> all resident (grid barrier safe)
#define NTHR 256
#define GC 16              // gate columns per CTA (4 h-cols x 4 gates)
#define JPC 4              // h columns per CTA (128*4 = 512 = H)
#define CHUNK 128
#define NCHUNK 8

// shared memory layout (in floats)
#define WSM_OFF 0          // [1024][16] weight slice        = 16384 floats
#define ZSM_OFF 16384      // [128][64] transposed z chunk   =  8192 floats
#define RED_OFF 24576      // [4][64][20] k-split partials   =  5120 floats
#define BIAS_OFF 29696     // [16]
#define SMEM_FLOATS 29712
#define SMEM_BYTES (SMEM_FLOATS * 4)

__device__ unsigned g_bar_count;
__device__ unsigned g_bar_gen;

__device__ __forceinline__ uint64_t pack2(float a, float b) {
    uint64_t r;
    asm("mov.b64 %0, {%1, %2};" : "=l"(r) : "f"(a), "f"(b));
    return r;
}
__device__ __forceinline__ void ffma2(uint64_t& d, uint64_t a, uint64_t b) {
    // packed fp32x2 FMA (Blackwell): 2 MACs/lane/instr, 2x SIMT fp32 rate
    asm("fma.rn.f32x2 %0, %1, %2, %0;" : "+l"(d) : "l"(a), "l"(b));
}

__device__ __forceinline__ void grid_sync() {
    __threadfence();       // every thread releases its h stores
    __syncthreads();
    if (threadIdx.x == 0) {
        unsigned g = *(volatile unsigned*)&g_bar_gen;
        if (atomicAdd(&g_bar_count, 1u) == gridDim.x - 1u) {
            atomicExch(&g_bar_count, 0u);
            __threadfence();
            atomicExch(&g_bar_gen, g + 1u);
        } else {
            while (*(volatile unsigned*)&g_bar_gen == g) { __nanosleep(32); }
        }
        __threadfence();   // acquire other CTAs' h stores
    }
    __syncthreads();
}

__global__ void __launch_bounds__(NTHR, 1)
lstm_persist_kernel(const float* __restrict__ x, const float* __restrict__ W,
                    const float* __restrict__ U, const float* __restrict__ bias,
                    float* out, long long out_elems)
{
    extern __shared__ float sm[];
    float* Wsm    = sm + WSM_OFF;
    float* zsm    = sm + ZSM_OFF;
    float* redsm  = sm + RED_OFF;
    float* biassm = sm + BIAS_OFF;

    const int tid = threadIdx.x;
    const int j0  = blockIdx.x * JPC;

    // ---- one-time: load [W;U] slice (1024 x 16) and bias into SMEM ----
    // local col c -> gate g = c>>2, dj = c&3 ; global weight col = g*512 + j0 + dj
    #pragma unroll 4
    for (int i = 0; i < 64; i++) {
        int idx = i * NTHR + tid;       // 0..16383
        int k = idx >> 4;
        int c = idx & 15;
        int G = (c >> 2) * NH + j0 + (c & 3);
        float v = (k < NI) ? W[k * (4 * NH) + G] : U[(k - NI) * (4 * NH) + G];
        Wsm[k * GC + c] = v;
    }
    if (tid < GC) {
        biassm[tid] = bias[(tid >> 2) * NH + j0 + (tid & 3)];
    }
    __syncthreads();

    // GEMM thread decomposition: 4x4 tile, 4-way K split
    const int cg = tid & 3;             // col group (4 cols)
    const int rg = (tid >> 2) & 15;     // row group (4 rows)
    const int kp = tid >> 6;            // k partition 0..3
    const int rb = rg << 2;
    const int cb = cg << 2;

    // epilogue decomposition: one (b, dj) per thread; c-state in register
    const int eb  = tid >> 2;           // 0..63
    const int edj = tid & 3;            // 0..3

    float creg = 0.f, hlast = 0.f;

    for (int t = 0; t < S_LEN; t++) {
        uint64_t acc[4][2];
        #pragma unroll
        for (int rr = 0; rr < 4; rr++) { acc[rr][0] = 0ull; acc[rr][1] = 0ull; }

        for (int ch = 0; ch < NCHUNK; ch++) {
            const int kbase = ch * CHUNK;
            const float* src = nullptr;
            bool zfill = false;
            if (kbase < NI) {
                src = x + (size_t)t * NB * NI + kbase;               // x_t
            } else if (t == 0) {
                zfill = true;                                         // h_{-1} = 0
            } else {
                src = out + (size_t)(t - 1) * NB * NH + (kbase - NI); // h_{t-1}
            }

            __syncthreads();  // previous chunk's compute done with zsm

            // stage chunk transposed: zsm[kk][b], XOR-swizzled.
            // unit = (bg, kk); consecutive tid -> consecutive kk (coalesced LDG)
            float4 v[8];
            #pragma unroll
            for (int i = 0; i < 8; i++) {
                int unit = i * NTHR + tid;
                int kk = unit & (CHUNK - 1);
                int b0 = (unit >> 7) << 2;
                if (zfill) {
                    v[i] = make_float4(0.f, 0.f, 0.f, 0.f);
                } else {
                    v[i].x = src[(b0 + 0) * 512 + kk];
                    v[i].y = src[(b0 + 1) * 512 + kk];
                    v[i].z = src[(b0 + 2) * 512 + kk];
                    v[i].w = src[(b0 + 3) * 512 + kk];
                }
            }
            #pragma unroll
            for (int i = 0; i < 8; i++) {
                int unit = i * NTHR + tid;
                int kk = unit & (CHUNK - 1);
                int b0 = (unit >> 7) << 2;
                int sw = ((kk >> 2) & 15) << 2;   // swizzle: conflict-free STS.128/LDS.128
                *(float4*)&zsm[kk * 64 + (b0 ^ sw)] = v[i];
            }
            __syncthreads();

            // compute: each thread 32 k-steps, 4 rows x 4 cols, packed f32x2
            const float* wrow = Wsm + kbase * GC + cb;
            const int kk0 = kp * 32;
            #pragma unroll 8
            for (int q = 0; q < 32; q++) {
                int kk = kk0 + q;
                int sw = ((kk >> 2) & 15) << 2;
                union { float4 f; uint64_t u[2]; } zv, wv;
                zv.f = *(const float4*)&zsm[kk * 64 + (rb ^ sw)];
                wv.f = *(const float4*)&wrow[kk * GC];
                uint64_t z;
                z = pack2(zv.f.x, zv.f.x); ffma2(acc[0][0], z, wv.u[0]); ffma2(acc[0][1], z, wv.u[1]);
                z = pack2(zv.f.y, zv.f.y); ffma2(acc[1][0], z, wv.u[0]); ffma2(acc[1][1], z, wv.u[1]);
                z = pack2(zv.f.z, zv.f.z); ffma2(acc[2][0], z, wv.u[0]); ffma2(acc[2][1], z, wv.u[1]);
                z = pack2(zv.f.w, zv.f.w); ffma2(acc[3][0], z, wv.u[0]); ffma2(acc[3][1], z, wv.u[1]);
            }
        }

        // ---- reduce the 4 K-partitions through SMEM ----
        #pragma unroll
        for (int rr = 0; rr < 4; rr++) {
            union { float4 f; uint64_t u[2]; } o;
            o.u[0] = acc[rr][0]; o.u[1] = acc[rr][1];
            *(float4*)&redsm[kp * 1280 + (rb + rr) * 20 + cb] = o.f;
        }
        __syncthreads();

        // ---- epilogue: gates -> (c, h); h written to out[t] ----
        float gs[4];
        #pragma unroll
        for (int g = 0; g < 4; g++) {
            int c = (g << 2) + edj;
            float s = biassm[c];
            #pragma unroll
            for (int p = 0; p < 4; p++) s += redsm[p * 1280 + eb * 20 + c];
            gs[g] = s;
        }
        float it = 1.f / (1.f + __expf(-gs[0]));
        float ft = 1.f / (1.f + __expf(-gs[1]));
        float gt = tanhf(gs[2]);
        float ot = 1.f / (1.f + __expf(-gs[3]));
        creg = ft * creg + it * gt;
        float hv = ot * tanhf(creg);
        hlast = hv;
        out[(size_t)t * NB * NH + (size_t)eb * NH + j0 + edj] = hv;

        grid_sync();   // h_t visible to all CTAs before t+1
    }

    // optional tail: (h_T, c_T) appended after hidden_seq if out has room
    long long base = (long long)S_LEN * NB * NH;
    long long bh   = (long long)NB * NH;
    if (base + bh <= out_elems)
        out[base + (size_t)eb * NH + j0 + edj] = hlast;
    if (base + 2 * bh <= out_elems)
        out[base + bh + (size_t)eb * NH + j0 + edj] = creg;
}

extern "C" void kernel_launch(void* const* d_in, const int* in_sizes, int n_in,
                              void* d_out, int out_size) {
    (void)in_sizes; (void)n_in;
    const float* x    = (const float*)d_in[0];
    const float* W    = (const float*)d_in[1];
    const float* U    = (const float*)d_in[2];
    const float* bias = (const float*)d_in[3];
    float* out = (float*)d_out;

    cudaFuncSetAttribute(lstm_persist_kernel,
                         cudaFuncAttributeMaxDynamicSharedMemorySize, SMEM_BYTES);
    lstm_persist_kernel<<<NCTA, NTHR, SMEM_BYTES>>>(x, W, U, bias, out,
                                                    (long long)out_size);
}

// round 7
// speedup vs baseline: 1.5250x; 1.5250x over previous
#include <cuda_runtime.h>
#include <cstdint>

// Problem: x[S,B,I] fp32, W[I,4H], U[H,4H], bias[4H]; S=2048,B=64,I=H=512
#define S_LEN 2048
#define NB 64
#define NI 512
#define NH 512
#define NCTA 128           // <= SM count -> all resident, grid barrier safe
#define NTHR 256
#define GC 16              // gate columns per CTA (4 h-cols x 4 gates)
#define JPC 4
#define CHUNK 128
#define NCHUNK 8
#define ZSTRIDE 68         // floats per k-row (64 + 4 pad: bank rotation)
#define ZBUF (CHUNK * ZSTRIDE)      // 8704 floats per z buffer
#define RSTRIDE 66         // reduction: 64 rows + 2 pad
#define RWARP (GC * RSTRIDE)        // 1056 floats per warp partition

// shared layout (floats)
#define WSM_OFF 0                                  // 1024 x 16 = 16384
#define ZSM_OFF 16384                              // 2 x 8704 = 17408
#define RED_OFF (ZSM_OFF + 2 * ZBUF)               // 33792; 8 x 1056 = 8448
#define BIAS_OFF (RED_OFF + 8 * RWARP)             // 42240
#define SMEM_FLOATS (BIAS_OFF + 16)                // 42256
#define SMEM_BYTES (SMEM_FLOATS * 4)               // 169024 B

__device__ unsigned g_bar_count;
__device__ unsigned g_bar_gen;

__device__ __forceinline__ uint64_t pack2(float a, float b) {
    uint64_t r;
    asm("mov.b64 %0, {%1, %2};" : "=l"(r) : "f"(a), "f"(b));
    return r;
}
__device__ __forceinline__ float2 unpack2(uint64_t v) {
    float2 f;
    asm("mov.b64 {%0, %1}, %2;" : "=f"(f.x), "=f"(f.y) : "l"(v));
    return f;
}
#define FFMA2(d, a, b) asm("fma.rn.f32x2 %0, %1, %2, %0;" : "+l"(d) : "l"(a), "l"(b))

__device__ __forceinline__ void grid_sync() {
    __threadfence();
    __syncthreads();
    if (threadIdx.x == 0) {
        unsigned g = *(volatile unsigned*)&g_bar_gen;
        if (atomicAdd(&g_bar_count, 1u) == gridDim.x - 1u) {
            atomicExch(&g_bar_count, 0u);
            __threadfence();
            atomicExch(&g_bar_gen, g + 1u);
        } else {
            while (*(volatile unsigned*)&g_bar_gen == g) { __nanosleep(32); }
        }
        __threadfence();
    }
    __syncthreads();
}

// Stage one chunk: thread owns column kk, 32 b-rows (b0 = 8i + 4*bhalf).
// Warp lanes have consecutive kk -> each scalar LDG is a coalesced 128B line.
__device__ __forceinline__ void stage_load(float4 v[8], const float* __restrict__ src,
                                           int kk, int bhalf) {
#pragma unroll
    for (int i = 0; i < 8; i++) {
        int b0 = 8 * i + 4 * bhalf;
        v[i].x = src[(b0 + 0) * 512 + kk];
        v[i].y = src[(b0 + 1) * 512 + kk];
        v[i].z = src[(b0 + 2) * 512 + kk];
        v[i].w = src[(b0 + 3) * 512 + kk];
    }
}

// Per-warp compute over its 16-k slice of the chunk.
// Lane tile: 16 rows (as 8 row-pairs, native f32x2 from ld.shared.v2.b64) x 2 cols.
__device__ __forceinline__ void compute_chunk(uint32_t zsa, const float* __restrict__ wbase,
                                              uint64_t acc[4][2][2], int wq0, int rg, int cg) {
#pragma unroll
    for (int q = 0; q < 16; q++) {
        int kk = wq0 + q;
        uint32_t za = zsa + (uint32_t)((kk * ZSTRIDE + rg * 4) * 4);
        uint64_t za0, zb0, za1, zb1, za2, zb2, za3, zb3;
        asm volatile("ld.shared.v2.u64 {%0,%1},[%2];" : "=l"(za0), "=l"(zb0) : "r"(za));
        asm volatile("ld.shared.v2.u64 {%0,%1},[%2];" : "=l"(za1), "=l"(zb1) : "r"(za + 64u));
        asm volatile("ld.shared.v2.u64 {%0,%1},[%2];" : "=l"(za2), "=l"(zb2) : "r"(za + 128u));
        asm volatile("ld.shared.v2.u64 {%0,%1},[%2];" : "=l"(za3), "=l"(zb3) : "r"(za + 192u));
        float2 wv = *(const float2*)(wbase + kk * GC + cg * 2);
        uint64_t wlo = pack2(wv.x, wv.x);
        uint64_t whi = pack2(wv.y, wv.y);
        FFMA2(acc[0][0][0], za0, wlo); FFMA2(acc[0][0][1], za0, whi);
        FFMA2(acc[0][1][0], zb0, wlo); FFMA2(acc[0][1][1], zb0, whi);
        FFMA2(acc[1][0][0], za1, wlo); FFMA2(acc[1][0][1], za1, whi);
        FFMA2(acc[1][1][0], zb1, wlo); FFMA2(acc[1][1][1], zb1, whi);
        FFMA2(acc[2][0][0], za2, wlo); FFMA2(acc[2][0][1], za2, whi);
        FFMA2(acc[2][1][0], zb2, wlo); FFMA2(acc[2][1][1], zb2, whi);
        FFMA2(acc[3][0][0], za3, wlo); FFMA2(acc[3][0][1], za3, whi);
        FFMA2(acc[3][1][0], zb3, wlo); FFMA2(acc[3][1][1], zb3, whi);
    }
}

__global__ void __launch_bounds__(NTHR, 1)
lstm_persist_kernel(const float* __restrict__ x, const float* __restrict__ W,
                    const float* __restrict__ U, const float* __restrict__ bias,
                    float* out, long long out_elems)
{
    extern __shared__ float sm[];
    float* Wsm    = sm + WSM_OFF;
    float* zsm    = sm + ZSM_OFF;
    float* redsm  = sm + RED_OFF;
    float* biassm = sm + BIAS_OFF;

    const int tid = threadIdx.x;
    const int j0  = blockIdx.x * JPC;

    // one-time: [W;U] slice (1024 x 16) + bias into smem
#pragma unroll 4
    for (int i = 0; i < 64; i++) {
        int idx = i * NTHR + tid;
        int k = idx >> 4;
        int c = idx & 15;
        int G = (c >> 2) * NH + j0 + (c & 3);
        float v = (k < NI) ? W[k * (4 * NH) + G] : U[(k - NI) * (4 * NH) + G];
        Wsm[k * GC + c] = v;
    }
    if (tid < GC) biassm[tid] = bias[(tid >> 2) * NH + j0 + (tid & 3)];
    __syncthreads();

    // compute decomposition
    const int w    = tid >> 5;          // warp = K partition within chunk
    const int lane = tid & 31;
    const int rg   = lane >> 3;         // row group: rows [rg*16, rg*16+16)
    const int cg   = lane & 7;          // col group: cols cg*2, cg*2+1
    const int wq0  = w * 16;
    // staging decomposition
    const int kk_s  = tid & 127;
    const int bhalf = tid >> 7;
    // epilogue decomposition
    const int eb  = tid >> 2;
    const int edj = tid & 3;

    uint32_t z0_sa = (uint32_t)__cvta_generic_to_shared(zsm);
    uint32_t z1_sa = z0_sa + (uint32_t)(ZBUF * 4);

    float creg = 0.f, hlast = 0.f;
    float4 v[8];

    // preload t=0, chunk 0 (x part)
    stage_load(v, x, kk_s, bhalf);

    for (int t = 0; t < S_LEN; t++) {
        uint64_t acc[4][2][2];
#pragma unroll
        for (int a = 0; a < 4; a++)
#pragma unroll
            for (int b = 0; b < 2; b++) { acc[a][b][0] = 0ull; acc[a][b][1] = 0ull; }

        const float* xt = x + (size_t)t * NB * NI;
        const float* hp = out + (size_t)(t - 1) * NB * NH;   // valid for t>0

#pragma unroll 1
        for (int ch = 0; ch < NCHUNK; ch++) {
            float*   zb  = (ch & 1) ? (zsm + ZBUF) : zsm;
            uint32_t zsa = (ch & 1) ? z1_sa : z0_sa;

            // store staged regs (bit-swapped b -> slot; stride-68 rotation => 4-phase STS.128)
#pragma unroll
            for (int i = 0; i < 8; i++) {
                int b0 = 8 * i + 4 * bhalf;
                int slot = ((b0 & 12) << 2) | ((b0 >> 2) & 12);
                *(float4*)&zb[kk_s * ZSTRIDE + slot] = v[i];
            }
            __syncthreads();

            // prefetch next chunk while computing this one
            if (ch < NCHUNK - 1) {
                int nc = ch + 1;
                if (nc < 4) {
                    stage_load(v, xt + nc * CHUNK, kk_s, bhalf);
                } else if (t == 0) {
#pragma unroll
                    for (int i = 0; i < 8; i++) v[i] = make_float4(0.f, 0.f, 0.f, 0.f);
                } else {
                    stage_load(v, hp + (nc - 4) * CHUNK, kk_s, bhalf);
                }
            }

            compute_chunk(zsa, Wsm + ch * CHUNK * GC, acc, wq0, rg, cg);
        }

        // reduction: per-warp partials, transposed [w][col][row], row-pairs as STS.64
#pragma unroll
        for (int vv = 0; vv < 4; vv++)
#pragma unroll
            for (int h = 0; h < 2; h++)
#pragma unroll
                for (int c = 0; c < 2; c++) {
                    float2 f = unpack2(acc[vv][h][c]);
                    int row = rg * 16 + vv * 4 + h * 2;
                    int col = cg * 2 + c;
                    *(float2*)&redsm[w * RWARP + col * RSTRIDE + row] = f;
                }
        __syncthreads();

        // epilogue: thread owns (eb, edj); sum 8 warp-partials per gate
        float gs[4];
#pragma unroll
        for (int g = 0; g < 4; g++) {
            int c = (g << 2) + edj;
            float s = biassm[c];
#pragma unroll
            for (int p = 0; p < 8; p++) s += redsm[p * RWARP + c * RSTRIDE + eb];
            gs[g] = s;
        }
        float it = 1.f / (1.f + __expf(-gs[0]));
        float ft = 1.f / (1.f + __expf(-gs[1]));
        float gt = tanhf(gs[2]);
        float ot = 1.f / (1.f + __expf(-gs[3]));
        creg = ft * creg + it * gt;
        float hv = ot * tanhf(creg);
        hlast = hv;
        out[(size_t)t * NB * NH + (size_t)eb * NH + j0 + edj] = hv;

        // prefetch next step's first x chunk before the barrier (pure overlap)
        if (t < S_LEN - 1) stage_load(v, x + (size_t)(t + 1) * NB * NI, kk_s, bhalf);

        grid_sync();
    }

    // optional tail: (h_T, c_T) after hidden_seq if out has room
    long long base = (long long)S_LEN * NB * NH;
    long long bh   = (long long)NB * NH;
    if (base + bh <= out_elems)
        out[base + (size_t)eb * NH + j0 + edj] = hlast;
    if (base + 2 * bh <= out_elems)
        out[base + bh + (size_t)eb * NH + j0 + edj] = creg;
}

extern "C" void kernel_launch(void* const* d_in, const int* in_sizes, int n_in,
                              void* d_out, int out_size) {
    (void)in_sizes; (void)n_in;
    const float* x    = (const float*)d_in[0];
    const float* W    = (const float*)d_in[1];
    const float* U    = (const float*)d_in[2];
    const float* bias = (const float*)d_in[3];
    float* out = (float*)d_out;

    cudaFuncSetAttribute(lstm_persist_kernel,
                         cudaFuncAttributeMaxDynamicSharedMemorySize, SMEM_BYTES);
    lstm_persist_kernel<<<NCTA, NTHR, SMEM_BYTES>>>(x, W, U, bias, out,
                                                    (long long)out_size);
}